// round 14
// baseline (speedup 1.0000x reference)
#include <cuda_runtime.h>
#include <cuda_bf16.h>
#include <math.h>
#include <stdint.h>

#define D       256
#define D4      64
#define NMAX    50000
#define EMAX    301000
#define BN_EPS  1e-5f
#define KCH     32
#define NCHUNK  8
#define STRIDE  40            // padded smem row stride in bf16 (80B) for k=32

// persistent scratch (no allocs allowed)
__device__ int            g_cnt[NMAX], g_off[NMAX], g_cur[NMAX];
__device__ int            g_idx[EMAX];
__device__ float          g_h  [(size_t)NMAX * D];
__device__ __nv_bfloat16  g_a_hi[(size_t)NMAX * D];
__device__ __nv_bfloat16  g_a_lo[(size_t)NMAX * D];
__device__ __nv_bfloat16  g_m_hi[(size_t)NMAX * D];
__device__ __nv_bfloat16  g_m_lo[(size_t)NMAX * D];
__device__ __nv_bfloat16  g_w1_hi[D * D], g_w1_lo[D * D];
__device__ __nv_bfloat16  g_w2_hi[D * D], g_w2_lo[D * D];

// ---------------- helpers ----------------------------------------------------
__device__ __forceinline__ uint32_t smem_u32(const void* p) {
    uint32_t a;
    asm("{ .reg .u64 t; cvta.to.shared.u64 t, %1; cvt.u32.u64 %0, t; }" : "=r"(a) : "l"(p));
    return a;
}
__device__ __forceinline__ void ldsm_x4(uint32_t* r, uint32_t addr) {
    asm volatile("ldmatrix.sync.aligned.m8n8.x4.shared.b16 {%0,%1,%2,%3}, [%4];"
        : "=r"(r[0]), "=r"(r[1]), "=r"(r[2]), "=r"(r[3]) : "r"(addr));
}
__device__ __forceinline__ void mma_bf16(float* c, const uint32_t* a, const uint32_t* b) {
    asm volatile("mma.sync.aligned.m16n8k16.row.col.f32.bf16.bf16.f32 "
        "{%0,%1,%2,%3}, {%4,%5,%6,%7}, {%8,%9}, {%0,%1,%2,%3};"
        : "+f"(c[0]), "+f"(c[1]), "+f"(c[2]), "+f"(c[3])
        : "r"(a[0]), "r"(a[1]), "r"(a[2]), "r"(a[3]), "r"(b[0]), "r"(b[1]));
}
__device__ __forceinline__ void split_bf16(float v, __nv_bfloat16& h, __nv_bfloat16& l) {
    h = __float2bfloat16(v);
    l = __float2bfloat16(v - __bfloat162float(h));
}
__device__ __forceinline__ void cp16(uint32_t saddr, const void* gaddr) {
    asm volatile("cp.async.cg.shared.global [%0], [%1], 16;" :: "r"(saddr), "l"(gaddr));
}
#define CP_COMMIT() asm volatile("cp.async.commit_group;" ::: "memory")
#define CP_WAIT(n)  asm volatile("cp.async.wait_group %0;" :: "n"(n) : "memory")

// per-buffer smem layout (bytes): four 128 x 32 bf16 tiles, stride 40
#define T_AHI  0
#define T_ALO  10240
#define T_BHI  20480
#define T_BLO  30720
#define BUF_BYTES 40960
#define SM_BYTES  (2 * BUF_BYTES)      // 80 KB -> 2 CTAs/SM (512 thr -> 128 regs)

// ====================== CSR build + weight split (fused) ====================
__global__ void count_split_kernel(const int* __restrict__ ei, int E,
                                   const float* __restrict__ W1,
                                   const float* __restrict__ W2) {
    int i = blockIdx.x * blockDim.x + threadIdx.x;
    if (i < E) atomicAdd(&g_cnt[ei[E + i]], 1);
    if (i < 2 * (D * D / 4)) {
        bool second = i >= (D * D / 4);
        int j = second ? i - D * D / 4 : i;
        float4 w = reinterpret_cast<const float4*>(second ? W2 : W1)[j];
        __nv_bfloat16* hi = second ? g_w2_hi : g_w1_hi;
        __nv_bfloat16* lo = second ? g_w2_lo : g_w1_lo;
        float v[4] = {w.x, w.y, w.z, w.w};
        union { uint2 u; __nv_bfloat16 b[4]; } ph, pl;
#pragma unroll
        for (int t = 0; t < 4; t++) split_bf16(v[t], ph.b[t], pl.b[t]);
        reinterpret_cast<uint2*>(hi)[j] = ph.u;
        reinterpret_cast<uint2*>(lo)[j] = pl.u;
    }
}
__global__ void scan_kernel(int N) {
    __shared__ int part[1024];
    int tid = threadIdx.x;
    int per = (N + 1023) >> 10;
    int lo = tid * per;
    int hi = lo + per; if (hi > N) hi = N;
    int s = 0;
    for (int i = lo; i < hi; i++) s += g_cnt[i];
    part[tid] = s;
    __syncthreads();
    for (int o = 1; o < 1024; o <<= 1) {
        int v = (tid >= o) ? part[tid - o] : 0;
        __syncthreads();
        part[tid] += v;
        __syncthreads();
    }
    int run = (tid == 0) ? 0 : part[tid - 1];
    for (int i = lo; i < hi; i++) {
        g_off[i] = run;
        g_cur[i] = run;
        run += g_cnt[i];
    }
}
__global__ void fill_kernel(const int* __restrict__ ei, int E) {
    int i = blockIdx.x * blockDim.x + threadIdx.x;
    if (i < E) {
        int d = ei[E + i];
        int p = atomicAdd(&g_cur[d], 1);
        g_idx[p] = i;
    }
}

// gather: agg = sum relu(x[src]+ea); h = 2x+agg -> g_h; bn1(h) split -> g_a
// (x2 unroll: best measured config, ~97us @ 73% DRAM)
__global__ void gather_kernel(const float* __restrict__ x,
                              const int* __restrict__ ei,
                              const float* __restrict__ ea,
                              const float* __restrict__ g1, const float* __restrict__ be1,
                              const float* __restrict__ mu1, const float* __restrict__ va1,
                              int N, int E) {
    int t = blockIdx.x * blockDim.x + threadIdx.x;
    int node = t >> 6, c = t & 63;
    if (node >= N) return;
    int off = g_off[node], deg = g_cnt[node];

    float4 sum = make_float4(0.f, 0.f, 0.f, 0.f);
    int j = 0;
    for (; j + 2 <= deg; j += 2) {
        int e0 = g_idx[off + j];
        int e1 = g_idx[off + j + 1];
        int s0 = ei[e0], s1 = ei[e1];
        float4 x0 = reinterpret_cast<const float4*>(x)[(size_t)s0 * D4 + c];
        float4 a0 = reinterpret_cast<const float4*>(ea)[(size_t)e0 * D4 + c];
        float4 x1 = reinterpret_cast<const float4*>(x)[(size_t)s1 * D4 + c];
        float4 a1 = reinterpret_cast<const float4*>(ea)[(size_t)e1 * D4 + c];
        sum.x += fmaxf(x0.x + a0.x, 0.f) + fmaxf(x1.x + a1.x, 0.f);
        sum.y += fmaxf(x0.y + a0.y, 0.f) + fmaxf(x1.y + a1.y, 0.f);
        sum.z += fmaxf(x0.z + a0.z, 0.f) + fmaxf(x1.z + a1.z, 0.f);
        sum.w += fmaxf(x0.w + a0.w, 0.f) + fmaxf(x1.w + a1.w, 0.f);
    }
    if (j < deg) {
        int e0 = g_idx[off + j];
        int s0 = ei[e0];
        float4 x0 = reinterpret_cast<const float4*>(x)[(size_t)s0 * D4 + c];
        float4 a0 = reinterpret_cast<const float4*>(ea)[(size_t)e0 * D4 + c];
        sum.x += fmaxf(x0.x + a0.x, 0.f);
        sum.y += fmaxf(x0.y + a0.y, 0.f);
        sum.z += fmaxf(x0.z + a0.z, 0.f);
        sum.w += fmaxf(x0.w + a0.w, 0.f);
    }
    float4 xn = reinterpret_cast<const float4*>(x)[(size_t)node * D4 + c];
    float4 h;
    h.x = 2.f * xn.x + sum.x; h.y = 2.f * xn.y + sum.y;
    h.z = 2.f * xn.z + sum.z; h.w = 2.f * xn.w + sum.w;
    reinterpret_cast<float4*>(g_h)[(size_t)node * D4 + c] = h;

    float4 ga = reinterpret_cast<const float4*>(g1)[c];
    float4 va = reinterpret_cast<const float4*>(va1)[c];
    float4 be = reinterpret_cast<const float4*>(be1)[c];
    float4 mu = reinterpret_cast<const float4*>(mu1)[c];
    float v[4];
    float sc;
    sc = ga.x * rsqrtf(va.x + BN_EPS); v[0] = h.x * sc + (be.x - mu.x * sc);
    sc = ga.y * rsqrtf(va.y + BN_EPS); v[1] = h.y * sc + (be.y - mu.y * sc);
    sc = ga.z * rsqrtf(va.z + BN_EPS); v[2] = h.z * sc + (be.z - mu.z * sc);
    sc = ga.w * rsqrtf(va.w + BN_EPS); v[3] = h.w * sc + (be.w - mu.w * sc);
    union { uint2 u; __nv_bfloat16 b[4]; } ph, pl;
#pragma unroll
    for (int q = 0; q < 4; q++) split_bf16(v[q], ph.b[q], pl.b[q]);
    reinterpret_cast<uint2*>(g_a_hi)[(size_t)node * D4 + c] = ph.u;
    reinterpret_cast<uint2*>(g_a_lo)[(size_t)node * D4 + c] = pl.u;
}

// ====================== GEMM machinery (256 thr, 8 warps) ===================
// CTA tile 128m x 128n (same as R13); warp tile 16m x 128n; 128-reg budget.
// staging: 256 threads, 8 cp16/thread (A 128x32 hi/lo + B 128x32 hi/lo)
__device__ __forceinline__ void stage_chunk(uint32_t sbase,
                                            const __nv_bfloat16* __restrict__ Ahi,
                                            const __nv_bfloat16* __restrict__ Alo,
                                            const __nv_bfloat16* __restrict__ Whi,
                                            const __nv_bfloat16* __restrict__ Wlo,
                                            int m0, int n0, int ch, int N, int tid) {
    int r  = tid >> 1;
    int kh = (tid & 1) * 16;                       // 16 bf16 = 32B (2 cp16)
    int arow = m0 + r; if (arow >= N) arow = 0;    // clamp: garbage rows unused
    size_t  agi = (size_t)arow * D + ch * KCH + kh;
    size_t  bgi = (size_t)(n0 + r) * D + ch * KCH + kh;
    uint32_t soff = (uint32_t)(r * STRIDE + kh) * 2;
    cp16(sbase + T_AHI + soff,      Ahi + agi);
    cp16(sbase + T_AHI + soff + 16, Ahi + agi + 8);
    cp16(sbase + T_ALO + soff,      Alo + agi);
    cp16(sbase + T_ALO + soff + 16, Alo + agi + 8);
    cp16(sbase + T_BHI + soff,      Whi + bgi);
    cp16(sbase + T_BHI + soff + 16, Whi + bgi + 8);
    cp16(sbase + T_BLO + soff,      Wlo + bgi);
    cp16(sbase + T_BLO + soff + 16, Wlo + bgi + 8);
}

// warp tile 16m x 128n; acc[16][4]; wm = wid (0..7)
__device__ __forceinline__ void mma_chunk(uint32_t base, int lane, int wm,
                                          float acc[16][4]) {
#pragma unroll
    for (int ks = 0; ks < 2; ks++) {
        uint32_t ah[4], al[4];
        {
            int row = wm * 16 + (lane & 15);
            int kk  = ks * 16 + ((lane >> 4) << 3);
            uint32_t ad = base + T_AHI + (uint32_t)(row * STRIDE + kk) * 2;
            ldsm_x4(ah, ad);
            ldsm_x4(al, ad + (T_ALO - T_AHI));
        }
#pragma unroll
        for (int nb = 0; nb < 8; nb++) {
            uint32_t bh[4], bl[4];
            int nrow = nb * 16 + (lane & 7) + ((lane >> 4) << 3);
            int kk   = ks * 16 + (((lane >> 3) & 1) << 3);
            uint32_t bd = base + T_BHI + (uint32_t)(nrow * STRIDE + kk) * 2;
            ldsm_x4(bh, bd);
            ldsm_x4(bl, bd + (T_BLO - T_BHI));
#pragma unroll
            for (int hf = 0; hf < 2; hf++) {
                float* c = acc[nb * 2 + hf];
                mma_bf16(c, ah, &bh[hf * 2]);
                mma_bf16(c, ah, &bl[hf * 2]);
                mma_bf16(c, al, &bh[hf * 2]);
            }
        }
    }
}

__device__ __forceinline__ void gemm_mainloop(uint32_t smb,
                                              const __nv_bfloat16* Ahi, const __nv_bfloat16* Alo,
                                              const __nv_bfloat16* Whi, const __nv_bfloat16* Wlo,
                                              int m0, int n0, int N, int tid,
                                              int lane, int wm,
                                              float acc[16][4]) {
    stage_chunk(smb, Ahi, Alo, Whi, Wlo, m0, n0, 0, N, tid);
    CP_COMMIT();
#pragma unroll
    for (int ch = 0; ch < NCHUNK; ch++) {
        if (ch < NCHUNK - 1) {
            stage_chunk(smb + ((ch + 1) & 1) * BUF_BYTES, Ahi, Alo, Whi, Wlo,
                        m0, n0, ch + 1, N, tid);
            CP_COMMIT();
            CP_WAIT(1);
        } else {
            CP_WAIT(0);
        }
        __syncthreads();
        mma_chunk(smb + (ch & 1) * BUF_BYTES, lane, wm, acc);
        __syncthreads();
    }
}

// ------------- GEMM1: mid = gelu(a @ W1^T + b1), split to bf16 --------------
__global__ void __launch_bounds__(256, 2)
gemm1_tc(const float* __restrict__ b1, int N) {
    extern __shared__ char sm[];
    uint32_t smb = smem_u32(sm);
    const int tid = threadIdx.x, lane = tid & 31, wm = tid >> 5;
    const int m0 = blockIdx.y * 128;
    const int n0 = blockIdx.x * 128;

    float acc[16][4];
#pragma unroll
    for (int b = 0; b < 16; b++)
#pragma unroll
        for (int c = 0; c < 4; c++) acc[b][c] = 0.f;

    gemm_mainloop(smb, g_a_hi, g_a_lo, g_w1_hi, g_w1_lo, m0, n0, N, tid, lane, wm, acc);

#pragma unroll
    for (int ni = 0; ni < 16; ni++) {
        int col = n0 + ni * 8 + (lane & 3) * 2;
        float2 bb = *reinterpret_cast<const float2*>(b1 + col);
#pragma unroll
        for (int h = 0; h < 2; h++) {
            int row = m0 + wm * 16 + (lane >> 2) + h * 8;
            if (row >= N) continue;
            float u0 = acc[ni][h * 2 + 0] + bb.x;
            float u1 = acc[ni][h * 2 + 1] + bb.y;
            float gl0 = 0.5f * u0 * (1.f + erff(u0 * 0.70710678118f));
            float gl1 = 0.5f * u1 * (1.f + erff(u1 * 0.70710678118f));
            union { uint32_t u; __nv_bfloat16 b[2]; } ph, pl;
            split_bf16(gl0, ph.b[0], pl.b[0]);
            split_bf16(gl1, ph.b[1], pl.b[1]);
            *reinterpret_cast<uint32_t*>(g_m_hi + (size_t)row * D + col) = ph.u;
            *reinterpret_cast<uint32_t*>(g_m_lo + (size_t)row * D + col) = pl.u;
        }
    }
}

// ------------- GEMM2: out = bn2(h + mid @ W2^T + b2) -------------------------
__global__ void __launch_bounds__(256, 2)
gemm2_tc(const float* __restrict__ b2,
         const float* __restrict__ g2, const float* __restrict__ be2,
         const float* __restrict__ mu2, const float* __restrict__ va2,
         float* __restrict__ out, int N) {
    extern __shared__ char sm[];
    uint32_t smb = smem_u32(sm);
    const int tid = threadIdx.x, lane = tid & 31, wm = tid >> 5;
    const int m0 = blockIdx.y * 128;
    const int n0 = blockIdx.x * 128;

    float acc[16][4];
#pragma unroll
    for (int b = 0; b < 16; b++)
#pragma unroll
        for (int c = 0; c < 4; c++) acc[b][c] = 0.f;

    gemm_mainloop(smb, g_m_hi, g_m_lo, g_w2_hi, g_w2_lo, m0, n0, N, tid, lane, wm, acc);

#pragma unroll
    for (int ni = 0; ni < 16; ni++) {
        int col = n0 + ni * 8 + (lane & 3) * 2;
        float2 bb = *reinterpret_cast<const float2*>(b2 + col);
        float2 ga = *reinterpret_cast<const float2*>(g2 + col);
        float2 be = *reinterpret_cast<const float2*>(be2 + col);
        float2 mu = *reinterpret_cast<const float2*>(mu2 + col);
        float2 va = *reinterpret_cast<const float2*>(va2 + col);
        float s0 = ga.x * rsqrtf(va.x + BN_EPS), t0 = be.x - mu.x * s0;
        float s1 = ga.y * rsqrtf(va.y + BN_EPS), t1 = be.y - mu.y * s1;
#pragma unroll
        for (int h = 0; h < 2; h++) {
            int row = m0 + wm * 16 + (lane >> 2) + h * 8;
            if (row >= N) continue;
            size_t gi = (size_t)row * D + col;
            float2 hv = *reinterpret_cast<const float2*>(g_h + gi);
            float f0 = acc[ni][h * 2 + 0] + bb.x;
            float f1 = acc[ni][h * 2 + 1] + bb.y;
            float2 o;
            o.x = (hv.x + f0) * s0 + t0;
            o.y = (hv.y + f1) * s1 + t1;
            *reinterpret_cast<float2*>(out + gi) = o;
        }
    }
}

// ---------------------------------------------------------------------------
extern "C" void kernel_launch(void* const* d_in, const int* in_sizes, int n_in,
                              void* d_out, int out_size) {
    const float* x   = (const float*)d_in[0];
    const int*   ei  = (const int*)d_in[1];
    const float* ea  = (const float*)d_in[2];
    const float* W1  = (const float*)d_in[3];
    const float* b1  = (const float*)d_in[4];
    const float* W2  = (const float*)d_in[5];
    const float* b2  = (const float*)d_in[6];
    const float* g1  = (const float*)d_in[7];
    const float* be1 = (const float*)d_in[8];
    const float* mu1 = (const float*)d_in[9];
    const float* va1 = (const float*)d_in[10];
    const float* g2  = (const float*)d_in[11];
    const float* be2 = (const float*)d_in[12];
    const float* mu2 = (const float*)d_in[13];
    const float* va2 = (const float*)d_in[14];
    float*       out = (float*)d_out;

    int N = in_sizes[0] / D;
    int E = in_sizes[2] / D;

    cudaFuncSetAttribute(gemm1_tc, cudaFuncAttributeMaxDynamicSharedMemorySize, SM_BYTES);
    cudaFuncSetAttribute(gemm2_tc, cudaFuncAttributeMaxDynamicSharedMemorySize, SM_BYTES);

    void* cnt_ptr = nullptr;
    cudaGetSymbolAddress(&cnt_ptr, g_cnt);
    cudaMemsetAsync(cnt_ptr, 0, (size_t)N * sizeof(int));

    count_split_kernel<<<(E + 255) / 256, 256>>>(ei, E, W1, W2);
    scan_kernel<<<1, 1024>>>(N);
    fill_kernel<<<(E + 255) / 256, 256>>>(ei, E);
    gather_kernel<<<(N * 64 + 255) / 256, 256>>>(x, ei, ea,
                                                 g1, be1, mu1, va1, N, E);

    dim3 grid(2, (N + 127) / 128);
    gemm1_tc<<<grid, 256, SM_BYTES>>>(b1, N);
    gemm2_tc<<<grid, 256, SM_BYTES>>>(b2, g2, be2, mu2, va2, out, N);
}

// round 15
// speedup vs baseline: 1.0554x; 1.0554x over previous
#include <cuda_runtime.h>
#include <cuda_bf16.h>
#include <math.h>
#include <stdint.h>

#define D       256
#define D4      64
#define NMAX    50000
#define EMAX    301000
#define BN_EPS  1e-5f
#define KCH     32
#define NCHUNK  8
#define STRIDE  40            // padded smem row stride in bf16 (80B) for k=32

// persistent scratch (no allocs allowed)
__device__ int            g_cnt[NMAX], g_off[NMAX], g_cur[NMAX];
__device__ int            g_idx[EMAX];
__device__ __nv_bfloat16  g_a_hi[(size_t)NMAX * D];
__device__ __nv_bfloat16  g_a_lo[(size_t)NMAX * D];
__device__ __nv_bfloat16  g_m_hi[(size_t)NMAX * D];
__device__ __nv_bfloat16  g_m_lo[(size_t)NMAX * D];
__device__ __nv_bfloat16  g_w1_hi[D * D], g_w1_lo[D * D];
__device__ __nv_bfloat16  g_w2_hi[D * D], g_w2_lo[D * D];

// ---------------- helpers ----------------------------------------------------
__device__ __forceinline__ uint32_t smem_u32(const void* p) {
    uint32_t a;
    asm("{ .reg .u64 t; cvta.to.shared.u64 t, %1; cvt.u32.u64 %0, t; }" : "=r"(a) : "l"(p));
    return a;
}
__device__ __forceinline__ void ldsm_x4(uint32_t* r, uint32_t addr) {
    asm volatile("ldmatrix.sync.aligned.m8n8.x4.shared.b16 {%0,%1,%2,%3}, [%4];"
        : "=r"(r[0]), "=r"(r[1]), "=r"(r[2]), "=r"(r[3]) : "r"(addr));
}
__device__ __forceinline__ void mma_bf16(float* c, const uint32_t* a, const uint32_t* b) {
    asm volatile("mma.sync.aligned.m16n8k16.row.col.f32.bf16.bf16.f32 "
        "{%0,%1,%2,%3}, {%4,%5,%6,%7}, {%8,%9}, {%0,%1,%2,%3};"
        : "+f"(c[0]), "+f"(c[1]), "+f"(c[2]), "+f"(c[3])
        : "r"(a[0]), "r"(a[1]), "r"(a[2]), "r"(a[3]), "r"(b[0]), "r"(b[1]));
}
__device__ __forceinline__ void split_bf16(float v, __nv_bfloat16& h, __nv_bfloat16& l) {
    h = __float2bfloat16(v);
    l = __float2bfloat16(v - __bfloat162float(h));
}
__device__ __forceinline__ void cp16(uint32_t saddr, const void* gaddr) {
    asm volatile("cp.async.cg.shared.global [%0], [%1], 16;" :: "r"(saddr), "l"(gaddr));
}
#define CP_COMMIT() asm volatile("cp.async.commit_group;" ::: "memory")
#define CP_WAIT(n)  asm volatile("cp.async.wait_group %0;" :: "n"(n) : "memory")

// per-buffer smem layout (bytes): four 128 x 32 bf16 tiles, stride 40
#define T_AHI  0
#define T_ALO  10240
#define T_BHI  20480
#define T_BLO  30720
#define BUF_BYTES 40960
#define SM_BYTES  (2 * BUF_BYTES)      // 80 KB -> 2 CTAs/SM

// ====================== CSR build + weight split (fused) ====================
__global__ void count_split_kernel(const int* __restrict__ ei, int E,
                                   const float* __restrict__ W1,
                                   const float* __restrict__ W2) {
    int i = blockIdx.x * blockDim.x + threadIdx.x;
    if (i < E) atomicAdd(&g_cnt[ei[E + i]], 1);
    if (i < 2 * (D * D / 4)) {
        bool second = i >= (D * D / 4);
        int j = second ? i - D * D / 4 : i;
        float4 w = reinterpret_cast<const float4*>(second ? W2 : W1)[j];
        __nv_bfloat16* hi = second ? g_w2_hi : g_w1_hi;
        __nv_bfloat16* lo = second ? g_w2_lo : g_w1_lo;
        float v[4] = {w.x, w.y, w.z, w.w};
        union { uint2 u; __nv_bfloat16 b[4]; } ph, pl;
#pragma unroll
        for (int t = 0; t < 4; t++) split_bf16(v[t], ph.b[t], pl.b[t]);
        reinterpret_cast<uint2*>(hi)[j] = ph.u;
        reinterpret_cast<uint2*>(lo)[j] = pl.u;
    }
}
__global__ void scan_kernel(int N) {
    __shared__ int part[1024];
    int tid = threadIdx.x;
    int per = (N + 1023) >> 10;
    int lo = tid * per;
    int hi = lo + per; if (hi > N) hi = N;
    int s = 0;
    for (int i = lo; i < hi; i++) s += g_cnt[i];
    part[tid] = s;
    __syncthreads();
    for (int o = 1; o < 1024; o <<= 1) {
        int v = (tid >= o) ? part[tid - o] : 0;
        __syncthreads();
        part[tid] += v;
        __syncthreads();
    }
    int run = (tid == 0) ? 0 : part[tid - 1];
    for (int i = lo; i < hi; i++) {
        g_off[i] = run;
        g_cur[i] = run;
        run += g_cnt[i];
    }
}
__global__ void fill_kernel(const int* __restrict__ ei, int E) {
    int i = blockIdx.x * blockDim.x + threadIdx.x;
    if (i < E) {
        int d = ei[E + i];
        int p = atomicAdd(&g_cur[d], 1);
        g_idx[p] = i;
    }
}

// gather: agg = sum relu(x[src]+ea); h = 2x+agg; bn1(h) split -> g_a
// (no g_h store: gemm2 reconstructs h from g_a via inverse bn1)
__global__ void gather_kernel(const float* __restrict__ x,
                              const int* __restrict__ ei,
                              const float* __restrict__ ea,
                              const float* __restrict__ g1, const float* __restrict__ be1,
                              const float* __restrict__ mu1, const float* __restrict__ va1,
                              int N, int E) {
    int t = blockIdx.x * blockDim.x + threadIdx.x;
    int node = t >> 6, c = t & 63;
    if (node >= N) return;
    int off = g_off[node], deg = g_cnt[node];

    float4 sum = make_float4(0.f, 0.f, 0.f, 0.f);
    int j = 0;
    for (; j + 2 <= deg; j += 2) {
        int e0 = g_idx[off + j];
        int e1 = g_idx[off + j + 1];
        int s0 = ei[e0], s1 = ei[e1];
        float4 x0 = reinterpret_cast<const float4*>(x)[(size_t)s0 * D4 + c];
        float4 a0 = reinterpret_cast<const float4*>(ea)[(size_t)e0 * D4 + c];
        float4 x1 = reinterpret_cast<const float4*>(x)[(size_t)s1 * D4 + c];
        float4 a1 = reinterpret_cast<const float4*>(ea)[(size_t)e1 * D4 + c];
        sum.x += fmaxf(x0.x + a0.x, 0.f) + fmaxf(x1.x + a1.x, 0.f);
        sum.y += fmaxf(x0.y + a0.y, 0.f) + fmaxf(x1.y + a1.y, 0.f);
        sum.z += fmaxf(x0.z + a0.z, 0.f) + fmaxf(x1.z + a1.z, 0.f);
        sum.w += fmaxf(x0.w + a0.w, 0.f) + fmaxf(x1.w + a1.w, 0.f);
    }
    if (j < deg) {
        int e0 = g_idx[off + j];
        int s0 = ei[e0];
        float4 x0 = reinterpret_cast<const float4*>(x)[(size_t)s0 * D4 + c];
        float4 a0 = reinterpret_cast<const float4*>(ea)[(size_t)e0 * D4 + c];
        sum.x += fmaxf(x0.x + a0.x, 0.f);
        sum.y += fmaxf(x0.y + a0.y, 0.f);
        sum.z += fmaxf(x0.z + a0.z, 0.f);
        sum.w += fmaxf(x0.w + a0.w, 0.f);
    }
    float4 xn = reinterpret_cast<const float4*>(x)[(size_t)node * D4 + c];
    float4 h;
    h.x = 2.f * xn.x + sum.x; h.y = 2.f * xn.y + sum.y;
    h.z = 2.f * xn.z + sum.z; h.w = 2.f * xn.w + sum.w;

    float4 ga = reinterpret_cast<const float4*>(g1)[c];
    float4 va = reinterpret_cast<const float4*>(va1)[c];
    float4 be = reinterpret_cast<const float4*>(be1)[c];
    float4 mu = reinterpret_cast<const float4*>(mu1)[c];
    float v[4];
    float sc;
    sc = ga.x * rsqrtf(va.x + BN_EPS); v[0] = h.x * sc + (be.x - mu.x * sc);
    sc = ga.y * rsqrtf(va.y + BN_EPS); v[1] = h.y * sc + (be.y - mu.y * sc);
    sc = ga.z * rsqrtf(va.z + BN_EPS); v[2] = h.z * sc + (be.z - mu.z * sc);
    sc = ga.w * rsqrtf(va.w + BN_EPS); v[3] = h.w * sc + (be.w - mu.w * sc);
    union { uint2 u; __nv_bfloat16 b[4]; } ph, pl;
#pragma unroll
    for (int q = 0; q < 4; q++) split_bf16(v[q], ph.b[q], pl.b[q]);
    reinterpret_cast<uint2*>(g_a_hi)[(size_t)node * D4 + c] = ph.u;
    reinterpret_cast<uint2*>(g_a_lo)[(size_t)node * D4 + c] = pl.u;
}

// ====================== GEMM machinery (512 thr, 16 warps) ==================
// (exact R9/R13 config: best measured, 2 CTAs/SM)
__device__ __forceinline__ void stage_chunk(uint32_t sbase,
                                            const __nv_bfloat16* __restrict__ Ahi,
                                            const __nv_bfloat16* __restrict__ Alo,
                                            const __nv_bfloat16* __restrict__ Whi,
                                            const __nv_bfloat16* __restrict__ Wlo,
                                            int m0, int n0, int ch, int N, int tid) {
    int r  = tid >> 2;
    int kq = (tid & 3) * 8;                        // 8 bf16 = 16B
    int arow = m0 + r; if (arow >= N) arow = 0;    // clamp: garbage rows unused
    size_t  agi = (size_t)arow * D + ch * KCH + kq;
    size_t  bgi = (size_t)(n0 + r) * D + ch * KCH + kq;
    uint32_t soff = (uint32_t)(r * STRIDE + kq) * 2;
    cp16(sbase + T_AHI + soff, Ahi + agi);
    cp16(sbase + T_ALO + soff, Alo + agi);
    cp16(sbase + T_BHI + soff, Whi + bgi);
    cp16(sbase + T_BLO + soff, Wlo + bgi);
}

// warp tile 16m x 64n; acc[8][4]
__device__ __forceinline__ void mma_chunk(uint32_t base, int lane, int wm, int wn,
                                          float acc[8][4]) {
#pragma unroll
    for (int ks = 0; ks < 2; ks++) {
        uint32_t ah[4], al[4];
        {
            int row = wm * 16 + (lane & 15);
            int kk  = ks * 16 + ((lane >> 4) << 3);
            uint32_t ad = base + T_AHI + (uint32_t)(row * STRIDE + kk) * 2;
            ldsm_x4(ah, ad);
            ldsm_x4(al, ad + (T_ALO - T_AHI));
        }
#pragma unroll
        for (int nb = 0; nb < 4; nb++) {
            uint32_t bh[4], bl[4];
            int nrow = wn * 64 + nb * 16 + (lane & 7) + ((lane >> 4) << 3);
            int kk   = ks * 16 + (((lane >> 3) & 1) << 3);
            uint32_t bd = base + T_BHI + (uint32_t)(nrow * STRIDE + kk) * 2;
            ldsm_x4(bh, bd);
            ldsm_x4(bl, bd + (T_BLO - T_BHI));
#pragma unroll
            for (int hf = 0; hf < 2; hf++) {
                float* c = acc[nb * 2 + hf];
                mma_bf16(c, ah, &bh[hf * 2]);
                mma_bf16(c, ah, &bl[hf * 2]);
                mma_bf16(c, al, &bh[hf * 2]);
            }
        }
    }
}

__device__ __forceinline__ void gemm_mainloop(uint32_t smb,
                                              const __nv_bfloat16* Ahi, const __nv_bfloat16* Alo,
                                              const __nv_bfloat16* Whi, const __nv_bfloat16* Wlo,
                                              int m0, int n0, int N, int tid,
                                              int lane, int wm, int wn,
                                              float acc[8][4]) {
    stage_chunk(smb, Ahi, Alo, Whi, Wlo, m0, n0, 0, N, tid);
    CP_COMMIT();
#pragma unroll
    for (int ch = 0; ch < NCHUNK; ch++) {
        if (ch < NCHUNK - 1) {
            stage_chunk(smb + ((ch + 1) & 1) * BUF_BYTES, Ahi, Alo, Whi, Wlo,
                        m0, n0, ch + 1, N, tid);
            CP_COMMIT();
            CP_WAIT(1);
        } else {
            CP_WAIT(0);
        }
        __syncthreads();
        mma_chunk(smb + (ch & 1) * BUF_BYTES, lane, wm, wn, acc);
        __syncthreads();
    }
}

// ------------- GEMM1: mid = gelu(a @ W1^T + b1), split to bf16 --------------
__global__ void __launch_bounds__(512, 2)
gemm1_tc(const float* __restrict__ b1, int N) {
    extern __shared__ char sm[];
    uint32_t smb = smem_u32(sm);
    const int tid = threadIdx.x, lane = tid & 31, wid = tid >> 5;
    const int wm = wid & 7, wn = wid >> 3;
    const int m0 = blockIdx.y * 128;
    const int n0 = blockIdx.x * 128;

    float acc[8][4];
#pragma unroll
    for (int b = 0; b < 8; b++)
#pragma unroll
        for (int c = 0; c < 4; c++) acc[b][c] = 0.f;

    gemm_mainloop(smb, g_a_hi, g_a_lo, g_w1_hi, g_w1_lo, m0, n0, N, tid, lane, wm, wn, acc);

#pragma unroll
    for (int ni = 0; ni < 8; ni++) {
        int col = n0 + wn * 64 + ni * 8 + (lane & 3) * 2;
        float2 bb = *reinterpret_cast<const float2*>(b1 + col);
#pragma unroll
        for (int h = 0; h < 2; h++) {
            int row = m0 + wm * 16 + (lane >> 2) + h * 8;
            if (row >= N) continue;
            float u0 = acc[ni][h * 2 + 0] + bb.x;
            float u1 = acc[ni][h * 2 + 1] + bb.y;
            float gl0 = 0.5f * u0 * (1.f + erff(u0 * 0.70710678118f));
            float gl1 = 0.5f * u1 * (1.f + erff(u1 * 0.70710678118f));
            union { uint32_t u; __nv_bfloat16 b[2]; } ph, pl;
            split_bf16(gl0, ph.b[0], pl.b[0]);
            split_bf16(gl1, ph.b[1], pl.b[1]);
            *reinterpret_cast<uint32_t*>(g_m_hi + (size_t)row * D + col) = ph.u;
            *reinterpret_cast<uint32_t*>(g_m_lo + (size_t)row * D + col) = pl.u;
        }
    }
}

// ------------- GEMM2: out = bn2(h + mid @ W2^T + b2) -------------------------
// h reconstructed from g_a via inverse bn1: h = (a_hi + a_lo - t1) / s1
__global__ void __launch_bounds__(512, 2)
gemm2_tc(const float* __restrict__ b2,
         const float* __restrict__ g1, const float* __restrict__ be1,
         const float* __restrict__ mu1, const float* __restrict__ va1,
         const float* __restrict__ g2, const float* __restrict__ be2,
         const float* __restrict__ mu2, const float* __restrict__ va2,
         float* __restrict__ out, int N) {
    extern __shared__ char sm[];
    uint32_t smb = smem_u32(sm);
    const int tid = threadIdx.x, lane = tid & 31, wid = tid >> 5;
    const int wm = wid & 7, wn = wid >> 3;
    const int m0 = blockIdx.y * 128;
    const int n0 = blockIdx.x * 128;

    float acc[8][4];
#pragma unroll
    for (int b = 0; b < 8; b++)
#pragma unroll
        for (int c = 0; c < 4; c++) acc[b][c] = 0.f;

    gemm_mainloop(smb, g_m_hi, g_m_lo, g_w2_hi, g_w2_lo, m0, n0, N, tid, lane, wm, wn, acc);

#pragma unroll
    for (int ni = 0; ni < 8; ni++) {
        int col = n0 + wn * 64 + ni * 8 + (lane & 3) * 2;
        float2 bb = *reinterpret_cast<const float2*>(b2 + col);
        float2 ga2 = *reinterpret_cast<const float2*>(g2 + col);
        float2 be2v = *reinterpret_cast<const float2*>(be2 + col);
        float2 mu2v = *reinterpret_cast<const float2*>(mu2 + col);
        float2 va2v = *reinterpret_cast<const float2*>(va2 + col);
        float s0 = ga2.x * rsqrtf(va2v.x + BN_EPS), t0 = be2v.x - mu2v.x * s0;
        float s1 = ga2.y * rsqrtf(va2v.y + BN_EPS), t1 = be2v.y - mu2v.y * s1;
        // inverse bn1 coefficients for this column pair
        float2 ga1 = *reinterpret_cast<const float2*>(g1 + col);
        float2 be1v = *reinterpret_cast<const float2*>(be1 + col);
        float2 mu1v = *reinterpret_cast<const float2*>(mu1 + col);
        float2 va1v = *reinterpret_cast<const float2*>(va1 + col);
        float s1a = ga1.x * rsqrtf(va1v.x + BN_EPS), t1a = be1v.x - mu1v.x * s1a;
        float s1b = ga1.y * rsqrtf(va1v.y + BN_EPS), t1b = be1v.y - mu1v.y * s1b;
        float inva = 1.f / s1a, invb = 1.f / s1b;
#pragma unroll
        for (int h = 0; h < 2; h++) {
            int row = m0 + wm * 16 + (lane >> 2) + h * 8;
            if (row >= N) continue;
            size_t gi = (size_t)row * D + col;
            union { uint32_t u; __nv_bfloat16 b[2]; } ah, al;
            ah.u = *reinterpret_cast<const uint32_t*>(g_a_hi + gi);
            al.u = *reinterpret_cast<const uint32_t*>(g_a_lo + gi);
            float a0 = __bfloat162float(ah.b[0]) + __bfloat162float(al.b[0]);
            float a1 = __bfloat162float(ah.b[1]) + __bfloat162float(al.b[1]);
            float h0 = (a0 - t1a) * inva;
            float h1 = (a1 - t1b) * invb;
            float f0 = acc[ni][h * 2 + 0] + bb.x;
            float f1 = acc[ni][h * 2 + 1] + bb.y;
            float2 o;
            o.x = (h0 + f0) * s0 + t0;
            o.y = (h1 + f1) * s1 + t1;
            *reinterpret_cast<float2*>(out + gi) = o;
        }
    }
}

// ---------------------------------------------------------------------------
extern "C" void kernel_launch(void* const* d_in, const int* in_sizes, int n_in,
                              void* d_out, int out_size) {
    const float* x   = (const float*)d_in[0];
    const int*   ei  = (const int*)d_in[1];
    const float* ea  = (const float*)d_in[2];
    const float* W1  = (const float*)d_in[3];
    const float* b1  = (const float*)d_in[4];
    const float* W2  = (const float*)d_in[5];
    const float* b2  = (const float*)d_in[6];
    const float* g1  = (const float*)d_in[7];
    const float* be1 = (const float*)d_in[8];
    const float* mu1 = (const float*)d_in[9];
    const float* va1 = (const float*)d_in[10];
    const float* g2  = (const float*)d_in[11];
    const float* be2 = (const float*)d_in[12];
    const float* mu2 = (const float*)d_in[13];
    const float* va2 = (const float*)d_in[14];
    float*       out = (float*)d_out;

    int N = in_sizes[0] / D;
    int E = in_sizes[2] / D;

    cudaFuncSetAttribute(gemm1_tc, cudaFuncAttributeMaxDynamicSharedMemorySize, SM_BYTES);
    cudaFuncSetAttribute(gemm2_tc, cudaFuncAttributeMaxDynamicSharedMemorySize, SM_BYTES);

    void* cnt_ptr = nullptr;
    cudaGetSymbolAddress(&cnt_ptr, g_cnt);
    cudaMemsetAsync(cnt_ptr, 0, (size_t)N * sizeof(int));

    count_split_kernel<<<(E + 255) / 256, 256>>>(ei, E, W1, W2);
    scan_kernel<<<1, 1024>>>(N);
    fill_kernel<<<(E + 255) / 256, 256>>>(ei, E);
    gather_kernel<<<(N * 64 + 255) / 256, 256>>>(x, ei, ea,
                                                 g1, be1, mu1, va1, N, E);

    dim3 grid(2, (N + 127) / 128);
    gemm1_tc<<<grid, 512, SM_BYTES>>>(b1, N);
    gemm2_tc<<<grid, 512, SM_BYTES>>>(b2, g1, be1, mu1, va1,
                                      g2, be2, mu2, va2, out, N);
}

// round 16
// speedup vs baseline: 1.0806x; 1.0239x over previous
#include <cuda_runtime.h>
#include <cuda_bf16.h>
#include <math.h>
#include <stdint.h>

#define D       256
#define D4      64
#define NMAX    50000
#define EMAX    301000
#define BN_EPS  1e-5f
#define KCH     32
#define NCHUNK  8
#define STRIDE  40            // padded smem row stride in bf16 (80B) for k=32

// persistent scratch (no allocs allowed)
__device__ int            g_cnt[NMAX], g_off[NMAX], g_cur[NMAX];
__device__ int            g_idx[EMAX];
__device__ __nv_bfloat16  g_a_hi[(size_t)NMAX * D];
__device__ __nv_bfloat16  g_a_lo[(size_t)NMAX * D];
__device__ __nv_bfloat16  g_m_hi[(size_t)NMAX * D];
__device__ __nv_bfloat16  g_m_lo[(size_t)NMAX * D];
__device__ __nv_bfloat16  g_w1_hi[D * D], g_w1_lo[D * D];
__device__ __nv_bfloat16  g_w2_hi[D * D], g_w2_lo[D * D];
// fused epilogue coefficients for gemm2: out = a*C0 + acc*S2 + CC
__device__ float          g_c0[D], g_s2[D], g_cc[D];

// ---------------- helpers ----------------------------------------------------
__device__ __forceinline__ uint32_t smem_u32(const void* p) {
    uint32_t a;
    asm("{ .reg .u64 t; cvta.to.shared.u64 t, %1; cvt.u32.u64 %0, t; }" : "=r"(a) : "l"(p));
    return a;
}
__device__ __forceinline__ void ldsm_x4(uint32_t* r, uint32_t addr) {
    asm volatile("ldmatrix.sync.aligned.m8n8.x4.shared.b16 {%0,%1,%2,%3}, [%4];"
        : "=r"(r[0]), "=r"(r[1]), "=r"(r[2]), "=r"(r[3]) : "r"(addr));
}
__device__ __forceinline__ void mma_bf16(float* c, const uint32_t* a, const uint32_t* b) {
    asm volatile("mma.sync.aligned.m16n8k16.row.col.f32.bf16.bf16.f32 "
        "{%0,%1,%2,%3}, {%4,%5,%6,%7}, {%8,%9}, {%0,%1,%2,%3};"
        : "+f"(c[0]), "+f"(c[1]), "+f"(c[2]), "+f"(c[3])
        : "r"(a[0]), "r"(a[1]), "r"(a[2]), "r"(a[3]), "r"(b[0]), "r"(b[1]));
}
__device__ __forceinline__ void split_bf16(float v, __nv_bfloat16& h, __nv_bfloat16& l) {
    h = __float2bfloat16(v);
    l = __float2bfloat16(v - __bfloat162float(h));
}
__device__ __forceinline__ void cp16(uint32_t saddr, const void* gaddr) {
    asm volatile("cp.async.cg.shared.global [%0], [%1], 16;" :: "r"(saddr), "l"(gaddr));
}
#define CP_COMMIT() asm volatile("cp.async.commit_group;" ::: "memory")
#define CP_WAIT(n)  asm volatile("cp.async.wait_group %0;" :: "n"(n) : "memory")

// per-buffer smem layout (bytes): four 128 x 32 bf16 tiles, stride 40
#define T_AHI  0
#define T_ALO  10240
#define T_BHI  20480
#define T_BLO  30720
#define BUF_BYTES 40960
#define SM_BYTES  (2 * BUF_BYTES)      // 80 KB -> 2 CTAs/SM

// ====================== CSR build + weight split (fused) ====================
__global__ void count_split_kernel(const int* __restrict__ ei, int E,
                                   const float* __restrict__ W1,
                                   const float* __restrict__ W2) {
    int i = blockIdx.x * blockDim.x + threadIdx.x;
    if (i < E) atomicAdd(&g_cnt[ei[E + i]], 1);
    if (i < 2 * (D * D / 4)) {
        bool second = i >= (D * D / 4);
        int j = second ? i - D * D / 4 : i;
        float4 w = reinterpret_cast<const float4*>(second ? W2 : W1)[j];
        __nv_bfloat16* hi = second ? g_w2_hi : g_w1_hi;
        __nv_bfloat16* lo = second ? g_w2_lo : g_w1_lo;
        float v[4] = {w.x, w.y, w.z, w.w};
        union { uint2 u; __nv_bfloat16 b[4]; } ph, pl;
#pragma unroll
        for (int t = 0; t < 4; t++) split_bf16(v[t], ph.b[t], pl.b[t]);
        reinterpret_cast<uint2*>(hi)[j] = ph.u;
        reinterpret_cast<uint2*>(lo)[j] = pl.u;
    }
}
// scan + fused gemm2 epilogue coefficients
__global__ void scan_kernel(int N,
                            const float* __restrict__ b2,
                            const float* __restrict__ g1, const float* __restrict__ be1,
                            const float* __restrict__ mu1, const float* __restrict__ va1,
                            const float* __restrict__ g2, const float* __restrict__ be2,
                            const float* __restrict__ mu2, const float* __restrict__ va2) {
    __shared__ int part[1024];
    int tid = threadIdx.x;
    if (tid < D) {
        float s1 = g1[tid] * rsqrtf(va1[tid] + BN_EPS);
        float t1 = be1[tid] - mu1[tid] * s1;
        float s2 = g2[tid] * rsqrtf(va2[tid] + BN_EPS);
        float t2 = be2[tid] - mu2[tid] * s2;
        float c0 = s2 / s1;
        g_c0[tid] = c0;
        g_s2[tid] = s2;
        g_cc[tid] = b2[tid] * s2 + t2 - t1 * c0;
    }
    int per = (N + 1023) >> 10;
    int lo = tid * per;
    int hi = lo + per; if (hi > N) hi = N;
    int s = 0;
    for (int i = lo; i < hi; i++) s += g_cnt[i];
    part[tid] = s;
    __syncthreads();
    for (int o = 1; o < 1024; o <<= 1) {
        int v = (tid >= o) ? part[tid - o] : 0;
        __syncthreads();
        part[tid] += v;
        __syncthreads();
    }
    int run = (tid == 0) ? 0 : part[tid - 1];
    for (int i = lo; i < hi; i++) {
        g_off[i] = run;
        g_cur[i] = run;
        run += g_cnt[i];
    }
}
__global__ void fill_kernel(const int* __restrict__ ei, int E) {
    int i = blockIdx.x * blockDim.x + threadIdx.x;
    if (i < E) {
        int d = ei[E + i];
        int p = atomicAdd(&g_cur[d], 1);
        g_idx[p] = i;
    }
}

// gather: agg = sum relu(x[src]+ea); h = 2x+agg; bn1(h) split -> g_a (no g_h)
__global__ void gather_kernel(const float* __restrict__ x,
                              const int* __restrict__ ei,
                              const float* __restrict__ ea,
                              const float* __restrict__ g1, const float* __restrict__ be1,
                              const float* __restrict__ mu1, const float* __restrict__ va1,
                              int N, int E) {
    int t = blockIdx.x * blockDim.x + threadIdx.x;
    int node = t >> 6, c = t & 63;
    if (node >= N) return;
    int off = g_off[node], deg = g_cnt[node];

    float4 sum = make_float4(0.f, 0.f, 0.f, 0.f);
    int j = 0;
    for (; j + 2 <= deg; j += 2) {
        int e0 = g_idx[off + j];
        int e1 = g_idx[off + j + 1];
        int s0 = ei[e0], s1 = ei[e1];
        float4 x0 = reinterpret_cast<const float4*>(x)[(size_t)s0 * D4 + c];
        float4 a0 = reinterpret_cast<const float4*>(ea)[(size_t)e0 * D4 + c];
        float4 x1 = reinterpret_cast<const float4*>(x)[(size_t)s1 * D4 + c];
        float4 a1 = reinterpret_cast<const float4*>(ea)[(size_t)e1 * D4 + c];
        sum.x += fmaxf(x0.x + a0.x, 0.f) + fmaxf(x1.x + a1.x, 0.f);
        sum.y += fmaxf(x0.y + a0.y, 0.f) + fmaxf(x1.y + a1.y, 0.f);
        sum.z += fmaxf(x0.z + a0.z, 0.f) + fmaxf(x1.z + a1.z, 0.f);
        sum.w += fmaxf(x0.w + a0.w, 0.f) + fmaxf(x1.w + a1.w, 0.f);
    }
    if (j < deg) {
        int e0 = g_idx[off + j];
        int s0 = ei[e0];
        float4 x0 = reinterpret_cast<const float4*>(x)[(size_t)s0 * D4 + c];
        float4 a0 = reinterpret_cast<const float4*>(ea)[(size_t)e0 * D4 + c];
        sum.x += fmaxf(x0.x + a0.x, 0.f);
        sum.y += fmaxf(x0.y + a0.y, 0.f);
        sum.z += fmaxf(x0.z + a0.z, 0.f);
        sum.w += fmaxf(x0.w + a0.w, 0.f);
    }
    float4 xn = reinterpret_cast<const float4*>(x)[(size_t)node * D4 + c];
    float4 h;
    h.x = 2.f * xn.x + sum.x; h.y = 2.f * xn.y + sum.y;
    h.z = 2.f * xn.z + sum.z; h.w = 2.f * xn.w + sum.w;

    float4 ga = reinterpret_cast<const float4*>(g1)[c];
    float4 va = reinterpret_cast<const float4*>(va1)[c];
    float4 be = reinterpret_cast<const float4*>(be1)[c];
    float4 mu = reinterpret_cast<const float4*>(mu1)[c];
    float v[4];
    float sc;
    sc = ga.x * rsqrtf(va.x + BN_EPS); v[0] = h.x * sc + (be.x - mu.x * sc);
    sc = ga.y * rsqrtf(va.y + BN_EPS); v[1] = h.y * sc + (be.y - mu.y * sc);
    sc = ga.z * rsqrtf(va.z + BN_EPS); v[2] = h.z * sc + (be.z - mu.z * sc);
    sc = ga.w * rsqrtf(va.w + BN_EPS); v[3] = h.w * sc + (be.w - mu.w * sc);
    union { uint2 u; __nv_bfloat16 b[4]; } ph, pl;
#pragma unroll
    for (int q = 0; q < 4; q++) split_bf16(v[q], ph.b[q], pl.b[q]);
    reinterpret_cast<uint2*>(g_a_hi)[(size_t)node * D4 + c] = ph.u;
    reinterpret_cast<uint2*>(g_a_lo)[(size_t)node * D4 + c] = pl.u;
}

// ====================== GEMM machinery (512 thr, 16 warps) ==================
// (exact R9/R13 config: best measured, 2 CTAs/SM)
__device__ __forceinline__ void stage_chunk(uint32_t sbase,
                                            const __nv_bfloat16* __restrict__ Ahi,
                                            const __nv_bfloat16* __restrict__ Alo,
                                            const __nv_bfloat16* __restrict__ Whi,
                                            const __nv_bfloat16* __restrict__ Wlo,
                                            int m0, int n0, int ch, int N, int tid) {
    int r  = tid >> 2;
    int kq = (tid & 3) * 8;                        // 8 bf16 = 16B
    int arow = m0 + r; if (arow >= N) arow = 0;    // clamp: garbage rows unused
    size_t  agi = (size_t)arow * D + ch * KCH + kq;
    size_t  bgi = (size_t)(n0 + r) * D + ch * KCH + kq;
    uint32_t soff = (uint32_t)(r * STRIDE + kq) * 2;
    cp16(sbase + T_AHI + soff, Ahi + agi);
    cp16(sbase + T_ALO + soff, Alo + agi);
    cp16(sbase + T_BHI + soff, Whi + bgi);
    cp16(sbase + T_BLO + soff, Wlo + bgi);
}

// warp tile 16m x 64n; acc[8][4]
__device__ __forceinline__ void mma_chunk(uint32_t base, int lane, int wm, int wn,
                                          float acc[8][4]) {
#pragma unroll
    for (int ks = 0; ks < 2; ks++) {
        uint32_t ah[4], al[4];
        {
            int row = wm * 16 + (lane & 15);
            int kk  = ks * 16 + ((lane >> 4) << 3);
            uint32_t ad = base + T_AHI + (uint32_t)(row * STRIDE + kk) * 2;
            ldsm_x4(ah, ad);
            ldsm_x4(al, ad + (T_ALO - T_AHI));
        }
#pragma unroll
        for (int nb = 0; nb < 4; nb++) {
            uint32_t bh[4], bl[4];
            int nrow = wn * 64 + nb * 16 + (lane & 7) + ((lane >> 4) << 3);
            int kk   = ks * 16 + (((lane >> 3) & 1) << 3);
            uint32_t bd = base + T_BHI + (uint32_t)(nrow * STRIDE + kk) * 2;
            ldsm_x4(bh, bd);
            ldsm_x4(bl, bd + (T_BLO - T_BHI));
#pragma unroll
            for (int hf = 0; hf < 2; hf++) {
                float* c = acc[nb * 2 + hf];
                mma_bf16(c, ah, &bh[hf * 2]);
                mma_bf16(c, ah, &bl[hf * 2]);
                mma_bf16(c, al, &bh[hf * 2]);
            }
        }
    }
}

__device__ __forceinline__ void gemm_mainloop(uint32_t smb,
                                              const __nv_bfloat16* Ahi, const __nv_bfloat16* Alo,
                                              const __nv_bfloat16* Whi, const __nv_bfloat16* Wlo,
                                              int m0, int n0, int N, int tid,
                                              int lane, int wm, int wn,
                                              float acc[8][4]) {
    stage_chunk(smb, Ahi, Alo, Whi, Wlo, m0, n0, 0, N, tid);
    CP_COMMIT();
#pragma unroll
    for (int ch = 0; ch < NCHUNK; ch++) {
        if (ch < NCHUNK - 1) {
            stage_chunk(smb + ((ch + 1) & 1) * BUF_BYTES, Ahi, Alo, Whi, Wlo,
                        m0, n0, ch + 1, N, tid);
            CP_COMMIT();
            CP_WAIT(1);
        } else {
            CP_WAIT(0);
        }
        __syncthreads();
        mma_chunk(smb + (ch & 1) * BUF_BYTES, lane, wm, wn, acc);
        __syncthreads();
    }
}

// ------------- GEMM1: mid = gelu(a @ W1^T + b1), split to bf16 --------------
__global__ void __launch_bounds__(512, 2)
gemm1_tc(const float* __restrict__ b1, int N) {
    extern __shared__ char sm[];
    uint32_t smb = smem_u32(sm);
    const int tid = threadIdx.x, lane = tid & 31, wid = tid >> 5;
    const int wm = wid & 7, wn = wid >> 3;
    const int m0 = blockIdx.y * 128;
    const int n0 = blockIdx.x * 128;

    float acc[8][4];
#pragma unroll
    for (int b = 0; b < 8; b++)
#pragma unroll
        for (int c = 0; c < 4; c++) acc[b][c] = 0.f;

    gemm_mainloop(smb, g_a_hi, g_a_lo, g_w1_hi, g_w1_lo, m0, n0, N, tid, lane, wm, wn, acc);

#pragma unroll
    for (int ni = 0; ni < 8; ni++) {
        int col = n0 + wn * 64 + ni * 8 + (lane & 3) * 2;
        float2 bb = *reinterpret_cast<const float2*>(b1 + col);
#pragma unroll
        for (int h = 0; h < 2; h++) {
            int row = m0 + wm * 16 + (lane >> 2) + h * 8;
            if (row >= N) continue;
            float u0 = acc[ni][h * 2 + 0] + bb.x;
            float u1 = acc[ni][h * 2 + 1] + bb.y;
            float gl0 = 0.5f * u0 * (1.f + erff(u0 * 0.70710678118f));
            float gl1 = 0.5f * u1 * (1.f + erff(u1 * 0.70710678118f));
            union { uint32_t u; __nv_bfloat16 b[2]; } ph, pl;
            split_bf16(gl0, ph.b[0], pl.b[0]);
            split_bf16(gl1, ph.b[1], pl.b[1]);
            *reinterpret_cast<uint32_t*>(g_m_hi + (size_t)row * D + col) = ph.u;
            *reinterpret_cast<uint32_t*>(g_m_lo + (size_t)row * D + col) = pl.u;
        }
    }
}

// ------------- GEMM2: out = a*C0 + acc*S2 + CC (fused bn1^-1 + bn2) ---------
__global__ void __launch_bounds__(512, 2)
gemm2_tc(float* __restrict__ out, int N) {
    extern __shared__ char sm[];
    uint32_t smb = smem_u32(sm);
    const int tid = threadIdx.x, lane = tid & 31, wid = tid >> 5;
    const int wm = wid & 7, wn = wid >> 3;
    const int m0 = blockIdx.y * 128;
    const int n0 = blockIdx.x * 128;

    float acc[8][4];
#pragma unroll
    for (int b = 0; b < 8; b++)
#pragma unroll
        for (int c = 0; c < 4; c++) acc[b][c] = 0.f;

    gemm_mainloop(smb, g_m_hi, g_m_lo, g_w2_hi, g_w2_lo, m0, n0, N, tid, lane, wm, wn, acc);

#pragma unroll
    for (int ni = 0; ni < 8; ni++) {
        int col = n0 + wn * 64 + ni * 8 + (lane & 3) * 2;
        float2 c0 = *reinterpret_cast<const float2*>(g_c0 + col);
        float2 s2 = *reinterpret_cast<const float2*>(g_s2 + col);
        float2 cc = *reinterpret_cast<const float2*>(g_cc + col);
#pragma unroll
        for (int h = 0; h < 2; h++) {
            int row = m0 + wm * 16 + (lane >> 2) + h * 8;
            if (row >= N) continue;
            size_t gi = (size_t)row * D + col;
            union { uint32_t u; __nv_bfloat16 b[2]; } ah, al;
            ah.u = *reinterpret_cast<const uint32_t*>(g_a_hi + gi);
            al.u = *reinterpret_cast<const uint32_t*>(g_a_lo + gi);
            float a0 = __bfloat162float(ah.b[0]) + __bfloat162float(al.b[0]);
            float a1 = __bfloat162float(ah.b[1]) + __bfloat162float(al.b[1]);
            float2 o;
            o.x = a0 * c0.x + acc[ni][h * 2 + 0] * s2.x + cc.x;
            o.y = a1 * c0.y + acc[ni][h * 2 + 1] * s2.y + cc.y;
            *reinterpret_cast<float2*>(out + gi) = o;
        }
    }
}

// ---------------------------------------------------------------------------
extern "C" void kernel_launch(void* const* d_in, const int* in_sizes, int n_in,
                              void* d_out, int out_size) {
    const float* x   = (const float*)d_in[0];
    const int*   ei  = (const int*)d_in[1];
    const float* ea  = (const float*)d_in[2];
    const float* W1  = (const float*)d_in[3];
    const float* b1  = (const float*)d_in[4];
    const float* W2  = (const float*)d_in[5];
    const float* b2  = (const float*)d_in[6];
    const float* g1  = (const float*)d_in[7];
    const float* be1 = (const float*)d_in[8];
    const float* mu1 = (const float*)d_in[9];
    const float* va1 = (const float*)d_in[10];
    const float* g2  = (const float*)d_in[11];
    const float* be2 = (const float*)d_in[12];
    const float* mu2 = (const float*)d_in[13];
    const float* va2 = (const float*)d_in[14];
    float*       out = (float*)d_out;

    int N = in_sizes[0] / D;
    int E = in_sizes[2] / D;

    cudaFuncSetAttribute(gemm1_tc, cudaFuncAttributeMaxDynamicSharedMemorySize, SM_BYTES);
    cudaFuncSetAttribute(gemm2_tc, cudaFuncAttributeMaxDynamicSharedMemorySize, SM_BYTES);

    void* cnt_ptr = nullptr;
    cudaGetSymbolAddress(&cnt_ptr, g_cnt);
    cudaMemsetAsync(cnt_ptr, 0, (size_t)N * sizeof(int));

    count_split_kernel<<<(E + 255) / 256, 256>>>(ei, E, W1, W2);
    scan_kernel<<<1, 1024>>>(N, b2, g1, be1, mu1, va1, g2, be2, mu2, va2);
    fill_kernel<<<(E + 255) / 256, 256>>>(ei, E);
    gather_kernel<<<(N * 64 + 255) / 256, 256>>>(x, ei, ea,
                                                 g1, be1, mu1, va1, N, E);

    dim3 grid(2, (N + 127) / 128);
    gemm1_tc<<<grid, 512, SM_BYTES>>>(b1, N);
    gemm2_tc<<<grid, 512, SM_BYTES>>>(out, N);
}